// round 6
// baseline (speedup 1.0000x reference)
#include <cuda_runtime.h>
#include <cstdint>

// EntropyCalculator: per-row histogram entropy.
//   x: [B, 64] int32, values in [0, 40)   out: [B, 1] float32
// H(row) = ln(64) - (1/64) * sum_v c_v * ln(c_v)
//
// Two launches: (A) fire-and-forget L2 prefetch of the whole input (64 MiB fits
// in the 126 MB L2) — retires immediately, DRAM fills proceed async;
// (B) histogram kernel consuming from L2 / in-flight fills.

#define NT 128          // threads per block = rows per tile
#define TS 20           // words per staged row (16) + 4 pad (16B-aligned rows for LDS.128)
#define NW 10           // 40 vocab bins as 4x8-bit byte counts per word

// ---- Kernel A: warm L2 -----------------------------------------------------
__global__ __launch_bounds__(256) void l2_warm_kernel(const char* __restrict__ x, int nlines)
{
    int idx = (blockIdx.x * 256 + threadIdx.x) * 2;
    if (idx + 1 < nlines) {
        const char* p = x + (size_t)idx * 128;
        asm volatile("prefetch.global.L2 [%0];" :: "l"(p));
        asm volatile("prefetch.global.L2 [%0];" :: "l"(p + 128));
    }
}

// ---- Kernel B: histogram entropy -------------------------------------------
__global__ __launch_bounds__(NT, 12) void entropy_hist_kernel(
    const int4* __restrict__ x, float* __restrict__ out, int B)
{
    __shared__ uint32_t tile[NT * TS];    // byte-packed ids, 16 words/row
    __shared__ uint32_t hist[NW * NT];    // per-thread byte-packed counts
    __shared__ float    lut[72];          // lut[c] = c*ln(c)/64

    const int tid = threadIdx.x;
    unsigned char* h8 = (unsigned char*)hist;
    const uint32_t t4 = (uint32_t)tid << 2;

    if (tid < 72) lut[tid] = (tid == 0) ? 0.0f : (float)tid * logf((float)tid) * 0.015625f;
    #pragma unroll
    for (int i = 0; i < NW; i++) hist[i * NT + tid] = 0u;

    // Stage 128 rows: coalesced int4 loads (L2-resident), PRMT-pack 4 ids/word.
    const int row0 = blockIdx.x * NT;
    const int rows_here = min(NT, B - row0);
    const int e_limit = rows_here * 16;
    const int4* gp = x + (size_t)row0 * 16;
    #pragma unroll
    for (int k = 0; k < 16; k++) {
        int e = tid + k * NT;
        if (e < e_limit) {
            int4 w = __ldcg(&gp[e]);
            uint32_t a = __byte_perm((uint32_t)w.x, (uint32_t)w.y, 0x0040);
            uint32_t b = __byte_perm((uint32_t)w.z, (uint32_t)w.w, 0x0040);
            tile[(e >> 4) * TS + (e & 15)] = __byte_perm(a, b, 0x5410);
        }
    }
    __syncthreads();

    const int row = row0 + tid;
    if (row < B) {
        // Histogram own row: 4 x LDS.128, 64 byte-count RMWs (bank = tid%32, private column)
        const uint4* my = (const uint4*)&tile[tid * TS];
        #pragma unroll
        for (int c = 0; c < 4; c++) {
            uint4 q = my[c];
            uint32_t ws[4] = {q.x, q.y, q.z, q.w};
            #pragma unroll
            for (int u = 0; u < 4; u++) {
                uint32_t p = ws[u];
                #pragma unroll
                for (int b = 0; b < 4; b++) {
                    uint32_t v = __byte_perm(p, 0u, 0x4440 + b);   // zero-extended byte b
                    // NT=128 byte addr: [0:1]=v&3, [2:8]=tid, [9:12]=v>>2 — disjoint
                    h8[(((v & 0x3Cu) << 7) | (v & 3u)) + t4]++;
                }
            }
        }

        // Entropy: H = ln(64) - sum c*ln(c)/64
        float acc = 0.0f;
        #pragma unroll
        for (int i = 0; i < NW; i++) {
            uint32_t w = hist[i * NT + tid];
            acc += lut[w & 0xFFu];
            acc += lut[(w >> 8) & 0xFFu];
            acc += lut[(w >> 16) & 0xFFu];
            acc += lut[w >> 24];
        }
        out[row] = 4.1588830833596718565f - acc;
    }
}

extern "C" void kernel_launch(void* const* d_in, const int* in_sizes, int n_in,
                              void* d_out, int out_size)
{
    const int4* x = (const int4*)d_in[0];
    float* out    = (float*)d_out;
    int B = in_sizes[0] / 64;                     // rows
    long long nbytes = (long long)in_sizes[0] * 4;
    int nlines = (int)(nbytes / 128);             // 128B cache lines

    int gridA = (nlines / 2 + 255) / 256;         // 2 lines per thread
    l2_warm_kernel<<<gridA, 256>>>((const char*)x, nlines);

    int gridB = (B + NT - 1) / NT;
    entropy_hist_kernel<<<gridB, NT>>>(x, out, B);
}

// round 7
// speedup vs baseline: 1.1196x; 1.1196x over previous
#include <cuda_runtime.h>
#include <cstdint>

// EntropyCalculator: per-row histogram entropy.
//   x: [B, 64] int32, values in [0, 40)   out: [B, 1] float32
// H(row) = ln(64) - (ln2/64) * sum_v c_v * log2(c_v)
//
// Key structure: 4 SEPARATE sub-histogram arrays so the smem byte-RMW
// dependence chain (compiler-serialized due to may-alias addresses) splits
// into 4 independent chains (depth 64 -> 16).

#define NT 128          // threads per block = rows per tile
#define TS 20           // words per staged row (16) + 4 pad (16B-aligned rows, conflict-free LDS.128)
#define NW 10           // 40 vocab bins as 4x8-bit byte counts per word

__global__ __launch_bounds__(NT, 7) void entropy_hist_kernel(
    const int4* __restrict__ x, float* __restrict__ out, int B)
{
    __shared__ uint32_t tile[NT * TS];   // byte-packed ids, 16 words/row
    __shared__ uint32_t h0[NW * NT];     // sub-hist: byte 0 of each packed word
    __shared__ uint32_t h1[NW * NT];     // sub-hist: byte 1
    __shared__ uint32_t h2[NW * NT];     // sub-hist: byte 2
    __shared__ uint32_t h3[NW * NT];     // sub-hist: byte 3

    const int tid = threadIdx.x;
    const uint32_t t4 = (uint32_t)tid << 2;
    unsigned char* p0 = (unsigned char*)h0;
    unsigned char* p1 = (unsigned char*)h1;
    unsigned char* p2 = (unsigned char*)h2;
    unsigned char* p3 = (unsigned char*)h3;

    #pragma unroll
    for (int i = 0; i < NW; i++) {
        h0[i * NT + tid] = 0u; h1[i * NT + tid] = 0u;
        h2[i * NT + tid] = 0u; h3[i * NT + tid] = 0u;
    }

    // Stage 128 rows: fully-coalesced int4 loads, PRMT-pack 4 ids/word.
    const int row0 = blockIdx.x * NT;
    const int rows_here = min(NT, B - row0);
    const int e_limit = rows_here * 16;
    const int4* gp = x + (size_t)row0 * 16;
    #pragma unroll
    for (int k = 0; k < 16; k++) {
        int e = tid + k * NT;
        if (e < e_limit) {
            int4 w = __ldcs(&gp[e]);
            uint32_t a = __byte_perm((uint32_t)w.x, (uint32_t)w.y, 0x0040);
            uint32_t b = __byte_perm((uint32_t)w.z, (uint32_t)w.w, 0x0040);
            tile[(e >> 4) * TS + (e & 15)] = __byte_perm(a, b, 0x5410);
        }
    }
    __syncthreads();

    const int row = row0 + tid;
    if (row < B) {
        // Histogram own row: 4 x LDS.128; per word, its 4 bytes go to 4 DISTINCT
        // shared arrays -> 4 independent RMW chains the compiler can interleave.
        // NT=128 byte addr: bits [0:1]=v&3, [2:8]=tid, [9:12]=v>>2 (disjoint fields).
        const uint4* my = (const uint4*)&tile[tid * TS];
        #pragma unroll
        for (int c = 0; c < 4; c++) {
            uint4 q = my[c];
            uint32_t ws[4] = {q.x, q.y, q.z, q.w};
            #pragma unroll
            for (int u = 0; u < 4; u++) {
                uint32_t p = ws[u];
                uint32_t v0 = __byte_perm(p, 0u, 0x4440);
                uint32_t v1 = __byte_perm(p, 0u, 0x4441);
                uint32_t v2 = __byte_perm(p, 0u, 0x4442);
                uint32_t v3 = __byte_perm(p, 0u, 0x4443);
                p0[(((v0 & 0x3Cu) << 7) | (v0 & 3u)) + t4]++;
                p1[(((v1 & 0x3Cu) << 7) | (v1 & 3u)) + t4]++;
                p2[(((v2 & 0x3Cu) << 7) | (v2 & 3u)) + t4]++;
                p3[(((v3 & 0x3Cu) << 7) | (v3 & 3u)) + t4]++;
            }
        }

        // Merge sub-hists (byte sums <= 64: no carry crossing) and accumulate
        // entropy arithmetically (MUFU.LG2) - no LUT, no conflicted LDS.
        float acc = 0.0f;
        #pragma unroll
        for (int i = 0; i < NW; i++) {
            uint32_t w = h0[i * NT + tid] + h1[i * NT + tid]
                       + h2[i * NT + tid] + h3[i * NT + tid];
            #pragma unroll
            for (int b = 0; b < 4; b++) {
                float cf = (float)((w >> (8 * b)) & 0xFFu);
                acc += cf * __log2f(fmaxf(cf, 1.0f));   // c = 0,1 -> 0
            }
        }
        // H = ln(64) - acc * ln2/64
        out[row] = 4.1588830833596718565f - acc * 0.010830424696159069f;
    }
}

extern "C" void kernel_launch(void* const* d_in, const int* in_sizes, int n_in,
                              void* d_out, int out_size)
{
    const int4* x = (const int4*)d_in[0];
    float* out    = (float*)d_out;
    int B = in_sizes[0] / 64;
    int grid = (B + NT - 1) / NT;
    entropy_hist_kernel<<<grid, NT>>>(x, out, B);
}